// round 10
// baseline (speedup 1.0000x reference)
#include <cuda_runtime.h>
#include <math.h>
#include <stdint.h>

#define BB 32
#define AA 9
#define HH 128
#define WW 128
#define NN (AA*HH*WW)      /* 147456 */
#define NF4 (NN/4)         /* 36864 float4 per image slab */
#define ITER (NF4/1024)    /* 36 */
#define PRE 6000
#define POST 300
#define CAP 8192
#define TGT 7000           /* raw-score cumcount target: >=PRE slack, <=CAP slack */
#define NMS_T 0.7f
#define NBIN 2048
#define FULLM 0xFFFFFFFFu

// Anchors: generate_anchors(16,[.5,1,2],[8,16,32]) — exact integers, verified vs numpy.
__constant__ float c_anch[AA*4] = {
   -84.f, -40.f,  99.f,  55.f,
  -176.f, -88.f, 191.f, 103.f,
  -360.f,-184.f, 375.f, 199.f,
   -56.f, -56.f,  71.f,  71.f,
  -120.f,-120.f, 135.f, 135.f,
  -248.f,-248.f, 263.f, 263.f,
   -36.f, -80.f,  51.f,  95.f,
   -80.f,-168.f,  95.f, 183.f,
  -168.f,-344.f, 183.f, 359.f
};

__device__ __forceinline__ unsigned keyOf(float f){
    unsigned u = __float_as_uint(f);
    return (u & 0x80000000u) ? ~u : (u | 0x80000000u);
}

__device__ __forceinline__ void decode_box(const float* __restrict__ pred,
                                           int b, int a, int y, int x,
                                           float imh, float imw,
                                           float& x1, float& y1, float& x2, float& y2,
                                           float& ws, float& hs){
    float sx = (float)(x*16), sy = (float)(y*16);
    float a0 = c_anch[a*4+0]+sx, a1 = c_anch[a*4+1]+sy;
    float a2 = c_anch[a*4+2]+sx, a3 = c_anch[a*4+3]+sy;
    float aw = a2-a0+1.0f, ah = a3-a1+1.0f;
    float cx = a0+0.5f*aw,  cy = a1+0.5f*ah;
    int base = ((b*4*AA + 4*a)*HH + y)*WW + x;
    float dx = pred[base];
    float dy = pred[base +   HH*WW];
    float dw = pred[base + 2*HH*WW];
    float dh = pred[base + 3*HH*WW];
    float pcx = dx*aw+cx, pcy = dy*ah+cy;
    float pw = expf(dw)*aw, ph = expf(dh)*ah;
    x1 = pcx-0.5f*pw; y1 = pcy-0.5f*ph; x2 = pcx+0.5f*pw; y2 = pcy+0.5f*ph;
    x1 = fminf(fmaxf(x1,0.0f), imw-1.0f);
    y1 = fminf(fmaxf(y1,0.0f), imh-1.0f);
    x2 = fminf(fmaxf(x2,0.0f), imw-1.0f);
    y2 = fminf(fmaxf(y2,0.0f), imh-1.0f);
    ws = x2-x1+1.0f; hs = y2-y1+1.0f;
}

// key -> bin (monotone). Fine bins (13-bit key granularity) over key >= keyOf(0.5).
__device__ __forceinline__ unsigned binOf(unsigned key){
    if (key >= 0xBF000000u){
        unsigned b = 1024u + ((key - 0xBF000000u) >> 13);
        return b > 2047u ? 2047u : b;
    }
    unsigned b = key >> 22;
    return b > 1023u ? 1023u : b;
}
__device__ __forceinline__ unsigned binStartKey(unsigned t){
    return (t >= 1024u) ? (0xBF000000u + ((t - 1024u) << 13)) : (t << 22);
}

// Register/shfl bitonic stage: thread owns 8 contiguous items, all indices static.
template<unsigned J>
__device__ __forceinline__ void reg_stage(unsigned long long r[8], unsigned tid, unsigned k){
    if constexpr (J >= 8u){
        constexpr unsigned lm = J >> 3;
        bool amLow = ((tid & lm) == 0u);
        #pragma unroll
        for (int c=0;c<8;c++){
            unsigned long long other = __shfl_xor_sync(FULLM, r[c], lm);
            bool d = (((tid*8u + (unsigned)c) & k) == 0u);  // desc
            bool takeMax = (d == amLow);
            unsigned long long mx = (r[c] > other) ? r[c] : other;
            unsigned long long mn = (r[c] > other) ? other : r[c];
            r[c] = takeMax ? mx : mn;
        }
    } else {
        #pragma unroll
        for (int c=0;c<8;c++){
            constexpr int JJ = (int)J;
            int p = c ^ JJ;
            if (p > c){
                bool d = (((tid*8u + (unsigned)c) & k) == 0u);
                if ((r[c] < r[p]) == d){
                    unsigned long long t=r[c]; r[c]=r[p]; r[p]=t;
                }
            }
        }
    }
    if constexpr (J > 1u) reg_stage<J/2u>(r, tid, k);
}

// ================= single fused per-image kernel =================
__global__ void __launch_bounds__(1024,1)
k_all(const float* __restrict__ cls, const float* __restrict__ pred,
      const float* __restrict__ info, float* __restrict__ out){
    extern __shared__ char smem[];
    unsigned long long* items = (unsigned long long*)smem;        // 64KB
    float4*   boxes = (float4*)(smem + CAP*8);                    // 96KB (after thresh)
    unsigned* h0    = (unsigned*)(smem + CAP*8);                  // overlaps boxes
    unsigned* h1    = h0 + NBIN;

    __shared__ float4   s_kept[POST];
    __shared__ int      s_wcnt[32];
    __shared__ unsigned s_warp[32];
    __shared__ unsigned s_K;
    __shared__ int      s_nk;

    int b = blockIdx.x;
    unsigned tid = threadIdx.x;
    int lane = tid & 31, wid = tid >> 5;
    const float4* sp = (const float4*)(cls + ((size_t)b*2*AA + AA)*HH*WW);
    float imh = __ldg(&info[b*3+0]);
    float imw = __ldg(&info[b*3+1]);
    float minsz = 16.0f*__ldg(&info[b*3+2]);

    // ---- init smem ----
    for (int i=tid;i<NBIN;i+=1024) h0[i]=0u;
    for (int i=tid;i<CAP;i+=1024) items[i]=0ull;
    __syncthreads();

    // ---- Phase H: raw-score histogram ----
    #pragma unroll 4
    for (int i=0;i<ITER;i++){
        float4 v = sp[i*1024 + tid];
        atomicAdd(&h0[binOf(keyOf(v.x))], 1u);
        atomicAdd(&h0[binOf(keyOf(v.y))], 1u);
        atomicAdd(&h0[binOf(keyOf(v.z))], 1u);
        atomicAdd(&h0[binOf(keyOf(v.w))], 1u);
    }
    __syncthreads();

    // ---- Phase T: suffix scan -> threshold key ----
    unsigned *src=h0, *dst=h1;
    for (int off=1; off<NBIN; off<<=1){
        for (int i=tid;i<NBIN;i+=1024)
            dst[i] = src[i] + ((i+off<NBIN)? src[i+off] : 0u);
        __syncthreads();
        unsigned* t = src; src = dst; dst = t;
    }
    for (int i=tid;i<NBIN;i+=1024){
        unsigned si = src[i];
        unsigned nx = (i+1<NBIN)? src[i+1] : 0u;
        if (si >= TGT && nx < TGT) s_K = binStartKey((unsigned)i);
    }
    __syncthreads();
    unsigned K = s_K;

    // ---- Phase C pass 1: count survivors (L2-resident re-read) ----
    unsigned ok[5] = {0u,0u,0u,0u,0u};
    int cntme = 0;
    #pragma unroll 4
    for (int i=0;i<ITER;i++){
        float4 v = sp[i*1024 + tid];
        unsigned g = 0u;
        if (keyOf(v.x) >= K) g |= 1u;
        if (keyOf(v.y) >= K) g |= 2u;
        if (keyOf(v.z) >= K) g |= 4u;
        if (keyOf(v.w) >= K) g |= 8u;
        ok[i>>3] |= g << ((i&7)*4);
        cntme += __popc(g);
    }
    int wtot = __reduce_add_sync(FULLM, cntme);
    if (lane==0) s_wcnt[wid] = wtot;
    __syncthreads();
    if (wid==0){
        int v = s_wcnt[lane];
        int inc = v;
        #pragma unroll
        for (int o=1;o<32;o<<=1){
            int t = __shfl_up_sync(FULLM, inc, o);
            if (lane >= o) inc += t;
        }
        s_wcnt[lane] = inc - v;   // exclusive warp base
    }
    __syncthreads();
    int base = s_wcnt[wid];

    // ---- Phase C pass 2: decode+filter survivors, write items (no atomics) ----
    for (int i=0;i<ITER;i++){
        unsigned g = (ok[i>>3] >> ((i&7)*4)) & 0xFu;
        unsigned any = __ballot_sync(FULLM, g != 0u);
        if (any){
            float4 v = sp[i*1024 + tid];
            float sv0=v.x, sv1=v.y, sv2=v.z, sv3=v.w;
            #pragma unroll
            for (int c=0;c<4;c++){
                unsigned m = __ballot_sync(FULLM, (g>>c)&1u);
                if ((g>>c)&1u){
                    int pos = base + __popc(m & ((1u<<lane)-1u));
                    if (pos < CAP){
                        int e = (i*1024 + (int)tid)*4 + c;
                        int a = e >> 14, rem = e & 16383;
                        int y = rem >> 7, x = rem & 127;
                        float x1,y1,x2,y2,ws,hs;
                        decode_box(pred,b,a,y,x,imh,imw,x1,y1,x2,y2,ws,hs);
                        float scv = (c==0)?sv0:((c==1)?sv1:((c==2)?sv2:sv3));
                        unsigned key = keyOf(scv);
                        if (!(ws >= minsz && hs >= minsz)) key = keyOf(-1e30f);
                        unsigned refidx = (unsigned)((y*WW + x)*AA + a);
                        items[pos] = ((unsigned long long)key << 32) | (unsigned)(~refidx);
                    }
                }
                base += __popc(m);
            }
        }
    }
    __syncthreads();

    // ---- Phase S: bitonic sort 8192 desc (regs/shfl + smem in-place) ----
    unsigned long long r[8];
    #pragma unroll
    for (int c=0;c<8;c++) r[c] = items[tid*8u + c];
    reg_stage<1u>(r, tid, 2u);
    reg_stage<2u>(r, tid, 4u);
    reg_stage<4u>(r, tid, 8u);
    reg_stage<8u>(r, tid, 16u);
    reg_stage<16u>(r, tid, 32u);
    reg_stage<32u>(r, tid, 64u);
    reg_stage<64u>(r, tid, 128u);
    reg_stage<128u>(r, tid, 256u);
    for (unsigned k=512u; k<=(unsigned)CAP; k<<=1){
        #pragma unroll
        for (int c=0;c<8;c++) items[tid*8u+c] = r[c];
        __syncthreads();
        for (unsigned j=k>>1; j>=256u; j>>=1){
            #pragma unroll
            for (int q4=0; q4<4; q4++){
                unsigned q = (unsigned)q4*1024u + tid;
                unsigned t = ((q & ~(j-1u)) << 1) | (q & (j-1u));
                unsigned ixj = t | j;
                unsigned long long va = items[t], vb = items[ixj];
                bool d = ((t & k) == 0u);
                if ((va < vb) == d){ items[t]=vb; items[ixj]=va; }
            }
            __syncthreads();
        }
        #pragma unroll
        for (int c=0;c<8;c++) r[c] = items[tid*8u+c];
        reg_stage<128u>(r, tid, k);
    }
    // write back fully sorted items (keys needed by NMS validity test)
    #pragma unroll
    for (int c=0;c<8;c++) items[tid*8u+c] = r[c];

    // ---- decode top-PRE candidate boxes into smem ----
    unsigned negk = keyOf(-1e30f);
    #pragma unroll
    for (int c=0;c<8;c++){
        int i = (int)tid*8 + c;
        if (i < PRE){
            unsigned key = (unsigned)(r[c] >> 32);
            float4 box = make_float4(0.f,0.f,0.f,0.f);
            if (key > negk){
                unsigned refidx = ~((unsigned)r[c]);
                int a = (int)(refidx % AA);
                int cell = (int)(refidx / AA);
                int x = cell & 127, y = cell >> 7;
                float x1,y1,x2,y2,ws,hs;
                decode_box(pred,b,a,y,x,imh,imw,x1,y1,x2,y2,ws,hs);
                box = make_float4(x1,y1,x2,y2);
            }
            boxes[i] = box;
        }
    }
    if (tid==0) s_nk = 0;
    __syncthreads();

    // ---- Phase N: incremental sweep NMS ----
    int nk = 0;
    const int NCHUNK = (PRE + 31) / 32;
    for (int ch = 0; ch < NCHUNK; ch++){
        int ci = ch*32 + lane;
        float4 bx = make_float4(0.f,0.f,0.f,0.f);
        bool valid = false;
        if (ci < PRE){
            bx = boxes[ci];
            valid = (((unsigned)(items[ci] >> 32)) > negk);
        }
        float area = (bx.z-bx.x+1.0f)*(bx.w-bx.y+1.0f);
        bool sup = !valid;
        for (int j = wid; j < nk; j += 32){
            float4 kb = s_kept[j];
            float ka = (kb.z-kb.x+1.0f)*(kb.w-kb.y+1.0f);
            float xx1=fmaxf(kb.x,bx.x), yy1=fmaxf(kb.y,bx.y);
            float xx2=fminf(kb.z,bx.z), yy2=fminf(kb.w,bx.w);
            float inter = fmaxf(xx2-xx1+1.0f,0.0f)*fmaxf(yy2-yy1+1.0f,0.0f);
            float iou = inter / fmaxf(ka + area - inter, 1e-6f);
            sup = sup | (iou > NMS_T);
        }
        unsigned m = __ballot_sync(FULLM, sup);
        if (lane == 0) s_warp[wid] = m;
        __syncthreads();
        if (wid == 0){
            unsigned supmask = __reduce_or_sync(FULLM, s_warp[lane]);
            unsigned alivemask = ~supmask;
            while (alivemask && nk < POST){
                int bp = __ffs(alivemask) - 1;
                float kx1 = __shfl_sync(FULLM, bx.x, bp);
                float ky1 = __shfl_sync(FULLM, bx.y, bp);
                float kx2 = __shfl_sync(FULLM, bx.z, bp);
                float ky2 = __shfl_sync(FULLM, bx.w, bp);
                if (lane == 0) s_kept[nk] = make_float4(kx1,ky1,kx2,ky2);
                nk++;
                alivemask &= ~(1u << bp);
                if (!alivemask || nk == POST) break;
                float ka = (kx2-kx1+1.0f)*(ky2-ky1+1.0f);
                float xx1=fmaxf(kx1,bx.x), yy1=fmaxf(ky1,bx.y);
                float xx2=fminf(kx2,bx.z), yy2=fminf(ky2,bx.w);
                float inter = fmaxf(xx2-xx1+1.0f,0.0f)*fmaxf(yy2-yy1+1.0f,0.0f);
                float iou = inter / fmaxf(ka + area - inter, 1e-6f);
                alivemask &= ~__ballot_sync(FULLM, iou > NMS_T);
            }
            if (lane == 0) s_nk = nk;
        }
        __syncthreads();
        nk = s_nk;
        if (nk >= POST) break;
    }

    // ---- output ----
    if (tid < POST){
        int row = (b*POST + (int)tid)*5;
        float4 kb = ((int)tid < nk) ? s_kept[tid] : make_float4(0.f,0.f,0.f,0.f);
        out[row+0] = (float)b;
        out[row+1] = kb.x; out[row+2] = kb.y; out[row+3] = kb.z; out[row+4] = kb.w;
    }
}

// ---------------- launcher ----------------
extern "C" void kernel_launch(void* const* d_in, const int* in_sizes, int n_in,
                              void* d_out, int out_size){
    const float* cls  = (const float*)d_in[0];
    const float* pred = (const float*)d_in[1];
    const float* info = (const float*)d_in[2];
    float* out = (float*)d_out;

    const int DYN = CAP*8 + PRE*16;   // 65536 + 96000 = 161536 bytes
    cudaFuncSetAttribute(k_all, cudaFuncAttributeMaxDynamicSharedMemorySize, DYN);
    k_all<<<BB, 1024, DYN>>>(cls, pred, info, out);
}